// round 3
// baseline (speedup 1.0000x reference)
#include <cuda_runtime.h>
#include <cstdint>
#include <cstddef>

// Problem dims
#define BB 256
#define SS 512
#define FF 64
#define HH 1024
#define OO 24

// ---------------- scratch (device globals; no allocs allowed) ----------------
constexpr size_t H_ELEMS = (size_t)SS * BB * HH;
__device__ float g_H1[H_ELEMS];            // layer0 hidden states, [S][B][H]
__device__ float g_H2[H_ELEMS];            // layer1 hidden states, [B][S][H]
__device__ float g_zero[BB * HH];          // never written -> always zero
__device__ float g_c[BB * HH];             // cell state (overwritten at t==0)
__device__ float g_part[128 * 256 * 24];   // FC partial sums
__device__ unsigned g_bar0[4 * SS];        // per-(batch-group, step) barriers, layer0
__device__ unsigned g_bar1[4 * SS];        // layer1

// ---------------- helpers ----------------
__device__ __forceinline__ unsigned f2tf(float f) {
    unsigned u;
    asm("cvt.rna.tf32.f32 %0, %1;" : "=r"(u) : "f"(f));
    return u;
}

__device__ __forceinline__ void mma8(float* d, const unsigned* a, const unsigned* b) {
    asm volatile(
        "mma.sync.aligned.m16n8k8.row.col.f32.tf32.tf32.f32 "
        "{%0,%1,%2,%3}, {%4,%5,%6,%7}, {%8,%9}, {%0,%1,%2,%3};\n"
        : "+f"(d[0]), "+f"(d[1]), "+f"(d[2]), "+f"(d[3])
        : "r"(a[0]), "r"(a[1]), "r"(a[2]), "r"(a[3]), "r"(b[0]), "r"(b[1]));
}

__device__ __forceinline__ float sigm(float x) { return 1.f / (1.f + __expf(-x)); }
__device__ __forceinline__ float tanh_(float x) {
    float a = fabsf(x);
    float e = __expf(-2.f * a);
    float t = (1.f - e) / (1.f + e);
    return copysignf(t, x);
}

// reset per-step barrier counters (one tiny node at graph start)
__global__ void bar_reset() {
    int i = blockIdx.x * blockDim.x + threadIdx.x;
    if (i < 4 * SS) { g_bar0[i] = 0; g_bar1[i] = 0; }
}

// ---------------- persistent LSTM layer kernel ----------------
// Grid (32, 4) = 128 CTAs, 128 threads. CTA tile: 64 batch x 32 h-cols,
// all 4 gates (effective GEMM N = 128). Loops over all SS timesteps with a
// software barrier among the 32 CTAs that share a batch group (blockIdx.y).
template <int KIN>
__global__ __launch_bounds__(128) void lstm_layer_persist(
    const float* __restrict__ A0base, size_t a0_tstride, size_t lda0,
    const float* __restrict__ hbase, size_t h_tstride, size_t ldh,
    const float* __restrict__ zero,
    const float* __restrict__ Wih, const float* __restrict__ Whh,
    const float* __restrict__ bih, const float* __restrict__ bhh,
    float* __restrict__ cst,
    float* __restrict__ houtbase, size_t hout_tstride, size_t hstride,
    unsigned* __restrict__ bar)
{
    constexpr int NCH = (KIN + HH) / 32;       // K chunks of 32
    __shared__ unsigned smem[8192];            // 32KB, unioned
    unsigned* sA = smem;                       // [64][36] tf32
    unsigned* sW = smem + 64 * 36;             // [128][36] tf32
    float* sC = (float*)smem;                  // [4][64][32] epilogue gates

    const int tid = threadIdx.x;
    const int n0 = blockIdx.x * 32;            // h-col base
    const int m0 = blockIdx.y * 64;            // batch base
    const int lane = tid & 31;
    const int warp = tid >> 5;
    const int wm = warp & 1;                   // batch half (32)
    const int wg = warp >> 1;                  // gate-pair
    const int g4 = lane >> 2, tig = lane & 3;
    unsigned* barg = bar + blockIdx.y * SS;

    for (int t = 0; t < SS; ++t) {
        const float* A0 = A0base + (size_t)t * a0_tstride + (size_t)m0 * lda0;
        const float* A1;
        size_t l1;
        if (t == 0) { A1 = zero + (size_t)m0 * HH; l1 = HH; }
        else        { A1 = hbase + (size_t)(t - 1) * h_tstride + (size_t)m0 * ldh; l1 = ldh; }

        float acc[2][8][4];
#pragma unroll
        for (int i = 0; i < 2; i++)
#pragma unroll
            for (int j = 0; j < 8; j++)
#pragma unroll
                for (int k = 0; k < 4; k++) acc[i][j][k] = 0.f;

        float4 rA[4];
        float4 rW[8];

        auto loadg = [&](int ch) {
            const int k0 = ch * 32;
            const float* As;
            size_t Al;
            if (k0 < KIN) { As = A0 + k0; Al = lda0; }
            else          { As = A1 + (k0 - KIN); Al = l1; }
#pragma unroll
            for (int i = 0; i < 4; i++) {
                int idx = tid + i * 128;
                int r = idx >> 3, c = idx & 7;
                rA[i] = *reinterpret_cast<const float4*>(As + (size_t)r * Al + c * 4);
            }
            const float* Ws;
            size_t Wl;
            int kw;
            if (k0 < KIN) { Ws = Wih; Wl = KIN; kw = k0; }
            else          { Ws = Whh; Wl = HH; kw = k0 - KIN; }
#pragma unroll
            for (int i = 0; i < 8; i++) {
                int idx = tid + i * 128;
                int r = idx >> 3, c = idx & 7;
                int g = (r >> 5) * HH + n0 + (r & 31);  // global gate row
                rW[i] = *reinterpret_cast<const float4*>(Ws + (size_t)g * Wl + kw + c * 4);
            }
        };
        auto stores = [&]() {
#pragma unroll
            for (int i = 0; i < 4; i++) {
                int idx = tid + i * 128;
                int r = idx >> 3, c = idx & 7;
                uint4 v = make_uint4(f2tf(rA[i].x), f2tf(rA[i].y), f2tf(rA[i].z), f2tf(rA[i].w));
                *reinterpret_cast<uint4*>(sA + r * 36 + c * 4) = v;
            }
#pragma unroll
            for (int i = 0; i < 8; i++) {
                int idx = tid + i * 128;
                int r = idx >> 3, c = idx & 7;
                uint4 v = make_uint4(f2tf(rW[i].x), f2tf(rW[i].y), f2tf(rW[i].z), f2tf(rW[i].w));
                *reinterpret_cast<uint4*>(sW + r * 36 + c * 4) = v;
            }
        };

        loadg(0);
        for (int ch = 0; ch < NCH; ++ch) {
            __syncthreads();
            stores();
            __syncthreads();
            if (ch + 1 < NCH) loadg(ch + 1);   // prefetch overlaps mma
#pragma unroll
            for (int kk = 0; kk < 32; kk += 8) {
                unsigned a[2][4];
#pragma unroll
                for (int mf = 0; mf < 2; mf++) {
                    int r = wm * 32 + mf * 16 + g4;
                    a[mf][0] = sA[r * 36 + kk + tig];
                    a[mf][1] = sA[(r + 8) * 36 + kk + tig];
                    a[mf][2] = sA[r * 36 + kk + tig + 4];
                    a[mf][3] = sA[(r + 8) * 36 + kk + tig + 4];
                }
                unsigned b[8][2];
#pragma unroll
                for (int nf = 0; nf < 8; nf++) {
                    int n = wg * 64 + nf * 8 + g4;
                    b[nf][0] = sW[n * 36 + kk + tig];
                    b[nf][1] = sW[n * 36 + kk + tig + 4];
                }
#pragma unroll
                for (int mf = 0; mf < 2; mf++)
#pragma unroll
                    for (int nf = 0; nf < 8; nf++) mma8(acc[mf][nf], a[mf], b[nf]);
            }
        }
        __syncthreads();

        // scatter accumulators to sC[gate][b_local][h_local]
#pragma unroll
        for (int mf = 0; mf < 2; mf++) {
            int r0 = wm * 32 + mf * 16 + g4;
#pragma unroll
            for (int nf = 0; nf < 8; nf++) {
                int gate = 2 * wg + (nf >> 2);
                int hc = (nf & 3) * 8 + 2 * tig;
                sC[(gate * 64 + r0) * 32 + hc]         = acc[mf][nf][0];
                sC[(gate * 64 + r0) * 32 + hc + 1]     = acc[mf][nf][1];
                sC[(gate * 64 + r0 + 8) * 32 + hc]     = acc[mf][nf][2];
                sC[(gate * 64 + r0 + 8) * 32 + hc + 1] = acc[mf][nf][3];
            }
        }
        __syncthreads();

        // LSTM cell (fp32)
        float* hout = houtbase + (size_t)t * hout_tstride;
        for (int idx = tid; idx < 64 * 32; idx += 128) {
            int bl = idx >> 5, hl = idx & 31;
            int hg = n0 + hl;
            float gi = sC[(0 * 64 + bl) * 32 + hl] + bih[hg] + bhh[hg];
            float gf = sC[(1 * 64 + bl) * 32 + hl] + bih[HH + hg] + bhh[HH + hg];
            float gg = sC[(2 * 64 + bl) * 32 + hl] + bih[2 * HH + hg] + bhh[2 * HH + hg];
            float go = sC[(3 * 64 + bl) * 32 + hl] + bih[3 * HH + hg] + bhh[3 * HH + hg];
            size_t b = (size_t)(m0 + bl);
            float cold = (t == 0) ? 0.f : cst[b * HH + hg];
            float cnew = sigm(gf) * cold + sigm(gi) * tanh_(gg);
            float hnew = sigm(go) * tanh_(cnew);
            cst[b * HH + hg] = cnew;
            hout[b * hstride + hg] = hnew;
        }

        // barrier among the 32 CTAs of this batch group: h[t] must be fully
        // written (and visible) before anyone reads it at step t+1.
        if (t + 1 < SS) {
            __syncthreads();
            __threadfence();
            if (tid == 0) {
                atomicAdd(&barg[t], 1u);
                while (*(volatile unsigned*)&barg[t] < 32u) { }
                __threadfence();
            }
            __syncthreads();
        }
    }
}

// ---------------- final FC: out[b,o] = H2flat[b,:] . fcW[o,:] + fcb[o] ----------------
__global__ __launch_bounds__(256) void fc_partial(
    const float* __restrict__ H2, const float* __restrict__ fcW,
    float* __restrict__ part)
{
    __shared__ float sH[32 * 132];
    __shared__ float sWf[24 * 132];
    const int tid = threadIdx.x;
    const int btile = blockIdx.x;  // 0..7  (32 batches each)
    const int kc = blockIdx.y;     // 0..127 (4096 k each)
    const int bl = tid >> 3, osub = tid & 7;
    const size_t KTOT = (size_t)SS * HH;  // 524288
    float acc[3] = {0.f, 0.f, 0.f};

    for (int k0 = kc * 4096; k0 < kc * 4096 + 4096; k0 += 128) {
#pragma unroll
        for (int i = 0; i < 4; i++) {
            int idx = tid + i * 256;
            int r = idx >> 5, c4 = idx & 31;
            *reinterpret_cast<float4*>(sH + r * 132 + c4 * 4) =
                *reinterpret_cast<const float4*>(H2 + (size_t)(btile * 32 + r) * KTOT + k0 + c4 * 4);
        }
#pragma unroll
        for (int i = 0; i < 3; i++) {
            int idx = tid + i * 256;
            int r = idx >> 5, c4 = idx & 31;
            *reinterpret_cast<float4*>(sWf + r * 132 + c4 * 4) =
                *reinterpret_cast<const float4*>(fcW + (size_t)r * KTOT + k0 + c4 * 4);
        }
        __syncthreads();
#pragma unroll 8
        for (int kk = 0; kk < 128; kk++) {
            float a = sH[bl * 132 + kk];
            acc[0] += a * sWf[(osub * 3 + 0) * 132 + kk];
            acc[1] += a * sWf[(osub * 3 + 1) * 132 + kk];
            acc[2] += a * sWf[(osub * 3 + 2) * 132 + kk];
        }
        __syncthreads();
    }
    int b = btile * 32 + bl;
#pragma unroll
    for (int j = 0; j < 3; j++)
        part[((size_t)kc * 256 + b) * 24 + osub * 3 + j] = acc[j];
}

__global__ void fc_reduce(const float* __restrict__ part, const float* __restrict__ fcb,
                          float* __restrict__ out)
{
    int id = blockIdx.x * 256 + threadIdx.x;
    if (id >= 256 * 24) return;
    int b = id / 24, o = id % 24;
    float s = fcb[o];
#pragma unroll 8
    for (int kc = 0; kc < 128; kc++) s += part[((size_t)kc * 256 + b) * 24 + o];
    out[(size_t)b * 24 + o] = s;
}

// ---------------- launch (6 graph nodes total) ----------------
extern "C" void kernel_launch(void* const* d_in, const int* in_sizes, int n_in,
                              void* d_out, int out_size)
{
    const float* x    = (const float*)d_in[0];
    const float* Wih0 = (const float*)d_in[1];
    const float* Whh0 = (const float*)d_in[2];
    const float* bih0 = (const float*)d_in[3];
    const float* bhh0 = (const float*)d_in[4];
    const float* Wih1 = (const float*)d_in[5];
    const float* Whh1 = (const float*)d_in[6];
    const float* bih1 = (const float*)d_in[7];
    const float* bhh1 = (const float*)d_in[8];
    const float* fcW  = (const float*)d_in[9];
    const float* fcb  = (const float*)d_in[10];

    float *H1p, *H2p, *zp, *cp, *pp;
    unsigned *b0p, *b1p;
    cudaGetSymbolAddress((void**)&H1p, g_H1);
    cudaGetSymbolAddress((void**)&H2p, g_H2);
    cudaGetSymbolAddress((void**)&zp, g_zero);
    cudaGetSymbolAddress((void**)&cp, g_c);
    cudaGetSymbolAddress((void**)&pp, g_part);
    cudaGetSymbolAddress((void**)&b0p, g_bar0);
    cudaGetSymbolAddress((void**)&b1p, g_bar1);

    bar_reset<<<8, 256>>>();

    dim3 grid(32, 4);
    // layer 0: A0(t) = x[:, t, :] (batch stride S*F); h stored [S][B][H]
    lstm_layer_persist<FF><<<grid, 128>>>(
        x, (size_t)FF, (size_t)SS * FF,
        H1p, (size_t)BB * HH, (size_t)HH,
        zp, Wih0, Whh0, bih0, bhh0,
        cp, H1p, (size_t)BB * HH, (size_t)HH, b0p);
    // layer 1: A0(t) = H1[t] ([B][H]); h stored [B][S][H] (FC-ready layout)
    lstm_layer_persist<HH><<<grid, 128>>>(
        H1p, (size_t)BB * HH, (size_t)HH,
        H2p, (size_t)HH, (size_t)SS * HH,
        zp, Wih1, Whh1, bih1, bhh1,
        cp, H2p, (size_t)HH, (size_t)SS * HH, b1p);

    fc_partial<<<dim3(8, 128), 256>>>(H2p, fcW, pp);
    fc_reduce<<<24, 256>>>(pp, fcb, (float*)d_out);
}

// round 5
// speedup vs baseline: 1.1907x; 1.1907x over previous
#include <cuda_runtime.h>
#include <cstdint>
#include <cstddef>

#define BB 256
#define SS 512
#define FF 64
#define HH 1024
#define OO 24

#define NCH0 34            // (64+1024)/32
#define NCH1 64            // (1024+1024)/32
#define STAGE_F 6912       // floats per stage: A 64*36 + B 128*36
#define SMEM_BYTES (3 * STAGE_F * 4 + 512)   // 83456

// ---------------- scratch (device globals; no allocs) ----------------
constexpr size_t H_ELEMS = (size_t)SS * BB * HH;
__device__ float g_H1[H_ELEMS];              // layer0 h, [S][B][H]
__device__ float g_H2[H_ELEMS];              // layer1 h, [B][S][H]
__device__ float g_zero[BB * HH];            // never written
__device__ float g_c[BB * HH];               // cell state
__device__ float g_part[128 * 256 * 24];     // FC partials
__device__ unsigned g_bar0[4 * SS];
__device__ unsigned g_bar1[4 * SS];
__device__ float g_Wr0[(size_t)32 * NCH0 * 128 * 32];  // 17MB permuted tf32 weights L0
__device__ float g_Wr1[(size_t)32 * NCH1 * 128 * 32];  // 32MB L1

// ---------------- helpers ----------------
__device__ __forceinline__ unsigned f2tf(float f) {
    unsigned u;
    asm("cvt.rna.tf32.f32 %0, %1;" : "=r"(u) : "f"(f));
    return u;
}
__device__ __forceinline__ void mma8(float* d, const unsigned* a, const unsigned* b) {
    asm volatile(
        "mma.sync.aligned.m16n8k8.row.col.f32.tf32.tf32.f32 "
        "{%0,%1,%2,%3}, {%4,%5,%6,%7}, {%8,%9}, {%0,%1,%2,%3};\n"
        : "+f"(d[0]), "+f"(d[1]), "+f"(d[2]), "+f"(d[3])
        : "r"(a[0]), "r"(a[1]), "r"(a[2]), "r"(a[3]), "r"(b[0]), "r"(b[1]));
}
__device__ __forceinline__ void cpa16(uint32_t dst, const void* src) {
    asm volatile("cp.async.cg.shared.global [%0], [%1], 16;" :: "r"(dst), "l"(src));
}
#define CP_COMMIT() asm volatile("cp.async.commit_group;" ::: "memory")
#define CP_WAIT(n)  asm volatile("cp.async.wait_group %0;" :: "n"(n) : "memory")
__device__ __forceinline__ uint32_t smem_u32(const void* p) {
    uint32_t a;
    asm("{ .reg .u64 t; cvta.to.shared.u64 t, %1; cvt.u32.u64 %0, t; }" : "=r"(a) : "l"(p));
    return a;
}
__device__ __forceinline__ float sigm(float x) { return 1.f / (1.f + __expf(-x)); }
__device__ __forceinline__ float tanh_(float x) {
    float a = fabsf(x);
    float e = __expf(-2.f * a);
    return copysignf((1.f - e) / (1.f + e), x);
}

__global__ void bar_reset() {
    int i = blockIdx.x * blockDim.x + threadIdx.x;
    if (i < 4 * SS) { g_bar0[i] = 0; g_bar1[i] = 0; }
}

// ---------------- weight convert + permute ----------------
// dst layout: d = ((ntile*NCH + c)*128 + j)*32 + p
//   j = gate*32 + hsub  (gate-major within CTA tile)
//   p(k) = (k&3)*8 + (k>>2)  -> inverse k(p) = (p&7)*4 + (p>>3)
__global__ void wcvt(const float* __restrict__ Wih, const float* __restrict__ Whh,
                     float* __restrict__ dst, int KIN, int NCH, size_t total)
{
    size_t d = (size_t)blockIdx.x * 256 + threadIdx.x;
    if (d >= total) return;
    int p = (int)(d & 31);
    int j = (int)((d >> 5) & 127);
    int rest = (int)(d >> 12);
    int c = rest % NCH, ntile = rest / NCH;
    int grow = (j >> 5) * HH + ntile * 32 + (j & 31);
    int k = c * 32 + ((p & 7) * 4 + (p >> 3));
    float v = (k < KIN) ? Wih[(size_t)grow * KIN + k]
                        : Whh[(size_t)grow * HH + (k - KIN)];
    dst[d] = __uint_as_float(f2tf(v));
}

// ---------------- persistent mma.sync LSTM layer ----------------
// Grid (32 ntiles, 4 batch groups) = 128 CTAs, 128 threads (4 warps).
// CTA tile: M=64 batch x N=128 gate-rows (gate-major: j = gate*32+hsub).
// Warp w owns N cols [w*32, w*32+32) = gate w. Warp tile 64x32.
template <int KIN>
__global__ __launch_bounds__(128, 1) void lstm_mma(
    const float* __restrict__ A0base, size_t a0_t, size_t lda0,
    const float* __restrict__ hbase, size_t h_t, size_t ldh,
    const float* __restrict__ zero,
    const float* __restrict__ Wr,
    const float* __restrict__ bih, const float* __restrict__ bhh,
    float* __restrict__ cst,
    float* __restrict__ houtbase, size_t hout_t, size_t hstride,
    unsigned* __restrict__ bar)
{
    constexpr int NCH = (KIN + HH) / 32;
    extern __shared__ float sm[];
    const uint32_t sb = smem_u32(sm);
    const int tid = threadIdx.x;
    const int lane = tid & 31, warp = tid >> 5;
    const int g4 = lane >> 2, tig = lane & 3;
    const int ntile = blockIdx.x;
    const int n0h = ntile * 32;
    const int m0 = blockIdx.y * 64;
    unsigned* barg = bar + blockIdx.y * SS;
    float* sBias = sm + 3 * STAGE_F;

    // biases for this CTA's 128 gate-rows
    if (tid < 128) {
        int grow = (tid >> 5) * HH + n0h + (tid & 31);
        sBias[tid] = bih[grow] + bhh[grow];
    }
    __syncthreads();

    for (int t = 0; t < SS; ++t) {
        const float* A0 = A0base + (size_t)t * a0_t + (size_t)m0 * lda0;
        const float* Ah = (t == 0) ? (zero + (size_t)m0 * HH)
                                   : (hbase + (size_t)(t - 1) * h_t + (size_t)m0 * ldh);
        const size_t ldah = (t == 0) ? (size_t)HH : ldh;

        auto issue = [&](int c) {
            const int st = c % 3;
            const uint32_t aB = sb + st * STAGE_F * 4;
            const uint32_t bB = aB + 64 * 36 * 4;
            const int k0 = c * 32;
            const float* As; size_t Al; int ka;
            if (k0 < KIN) { As = A0; Al = lda0; ka = k0; }
            else          { As = Ah; Al = ldah; ka = k0 - KIN; }
#pragma unroll
            for (int i = 0; i < 4; i++) {
                int idx = i * 128 + tid;
                int r = idx >> 3, c4 = idx & 7;
                cpa16(aB + r * 144 + c4 * 16, As + (size_t)r * Al + ka + c4 * 4);
            }
            const float* Bs = Wr + ((size_t)ntile * NCH + c) * 4096;
#pragma unroll
            for (int i = 0; i < 8; i++) {
                int seg = i * 128 + tid;
                cpa16(bB + (seg >> 3) * 144 + (seg & 7) * 16, Bs + seg * 4);
            }
            CP_COMMIT();
        };

        float acc[4][4][4];
#pragma unroll
        for (int mf = 0; mf < 4; mf++)
#pragma unroll
            for (int nf = 0; nf < 4; nf++)
#pragma unroll
                for (int q = 0; q < 4; q++) acc[mf][nf][q] = 0.f;

        issue(0); issue(1); issue(2);

        for (int c = 0; c < NCH; ++c) {
            if (c < NCH - 2)      { CP_WAIT(2); }
            else if (c == NCH - 2){ CP_WAIT(1); }
            else                  { CP_WAIT(0); }
            __syncthreads();

            const int st = c % 3;
            const float* sA = sm + st * STAGE_F;
            const float* sB = sA + 64 * 36;

            // B fragments: whole chunk (k-permuted), 8 regs per nf, 2x lds.128
            unsigned bp[4][8];
#pragma unroll
            for (int nf = 0; nf < 4; nf++) {
                const float* base = sB + (warp * 32 + nf * 8 + g4) * 36 + tig * 8;
                uint4 v0 = *reinterpret_cast<const uint4*>(base);
                uint4 v1 = *reinterpret_cast<const uint4*>(base + 4);
                bp[nf][0] = v0.x; bp[nf][1] = v0.y; bp[nf][2] = v0.z; bp[nf][3] = v0.w;
                bp[nf][4] = v1.x; bp[nf][5] = v1.y; bp[nf][6] = v1.z; bp[nf][7] = v1.w;
            }
#pragma unroll
            for (int kk8 = 0; kk8 < 4; kk8++) {
                const int kk = kk8 * 8;
                unsigned a[4][4];
#pragma unroll
                for (int mf = 0; mf < 4; mf++) {
                    int r = mf * 16 + g4;
                    a[mf][0] = f2tf(sA[r * 36 + kk + tig]);
                    a[mf][1] = f2tf(sA[(r + 8) * 36 + kk + tig]);
                    a[mf][2] = f2tf(sA[r * 36 + kk + tig + 4]);
                    a[mf][3] = f2tf(sA[(r + 8) * 36 + kk + tig + 4]);
                }
#pragma unroll
                for (int mf = 0; mf < 4; mf++)
#pragma unroll
                    for (int nf = 0; nf < 4; nf++) {
                        unsigned b2[2] = { bp[nf][kk8 * 2], bp[nf][kk8 * 2 + 1] };
                        mma8(acc[mf][nf], a[mf], b2);
                    }
            }
            __syncthreads();
            if (c + 3 < NCH) issue(c + 3);
        }

        // ---- epilogue: bounce accs through smem (sC aliases stage 0/1) ----
        float* sC = sm;   // [4 gates][64 b][32 h]
#pragma unroll
        for (int mf = 0; mf < 4; mf++) {
            int r = mf * 16 + g4;
#pragma unroll
            for (int nf = 0; nf < 4; nf++) {
                int col = nf * 8 + 2 * tig;
                *reinterpret_cast<float2*>(&sC[warp * 2048 + r * 32 + col]) =
                    make_float2(acc[mf][nf][0], acc[mf][nf][1]);
                *reinterpret_cast<float2*>(&sC[warp * 2048 + (r + 8) * 32 + col]) =
                    make_float2(acc[mf][nf][2], acc[mf][nf][3]);
            }
        }
        __syncthreads();

        float* hout = houtbase + (size_t)t * hout_t;
#pragma unroll
        for (int it = 0; it < 4; it++) {
            int idx4 = it * 128 + tid;
            int bl = idx4 >> 3, h4 = (idx4 & 7) * 4;
            float4 gi = *reinterpret_cast<float4*>(&sC[0 * 2048 + bl * 32 + h4]);
            float4 gf = *reinterpret_cast<float4*>(&sC[1 * 2048 + bl * 32 + h4]);
            float4 gg = *reinterpret_cast<float4*>(&sC[2 * 2048 + bl * 32 + h4]);
            float4 go = *reinterpret_cast<float4*>(&sC[3 * 2048 + bl * 32 + h4]);
            float4 b0 = *reinterpret_cast<float4*>(&sBias[0 * 32 + h4]);
            float4 b1 = *reinterpret_cast<float4*>(&sBias[32 + h4]);
            float4 b2 = *reinterpret_cast<float4*>(&sBias[64 + h4]);
            float4 b3 = *reinterpret_cast<float4*>(&sBias[96 + h4]);
            size_t b = (size_t)(m0 + bl);
            float4 cold = (t == 0) ? make_float4(0.f, 0.f, 0.f, 0.f)
                                   : *reinterpret_cast<float4*>(&cst[b * HH + n0h + h4]);
            float4 cn, hn;
            {
                float ci = sigm(gi.x + b0.x), cf = sigm(gf.x + b1.x);
                float cg = tanh_(gg.x + b2.x), co = sigm(go.x + b3.x);
                cn.x = cf * cold.x + ci * cg; hn.x = co * tanh_(cn.x);
            }
            {
                float ci = sigm(gi.y + b0.y), cf = sigm(gf.y + b1.y);
                float cg = tanh_(gg.y + b2.y), co = sigm(go.y + b3.y);
                cn.y = cf * cold.y + ci * cg; hn.y = co * tanh_(cn.y);
            }
            {
                float ci = sigm(gi.z + b0.z), cf = sigm(gf.z + b1.z);
                float cg = tanh_(gg.z + b2.z), co = sigm(go.z + b3.z);
                cn.z = cf * cold.z + ci * cg; hn.z = co * tanh_(cn.z);
            }
            {
                float ci = sigm(gi.w + b0.w), cf = sigm(gf.w + b1.w);
                float cg = tanh_(gg.w + b2.w), co = sigm(go.w + b3.w);
                cn.w = cf * cold.w + ci * cg; hn.w = co * tanh_(cn.w);
            }
            *reinterpret_cast<float4*>(&cst[b * HH + n0h + h4]) = cn;
            *reinterpret_cast<float4*>(&hout[b * hstride + n0h + h4]) = hn;
        }
        __syncthreads();

        // ---- batch-group barrier (32 CTAs) before anyone reads h[t] ----
        if (t + 1 < SS) {
            __threadfence();
            if (tid == 0) {
                atomicAdd(&barg[t], 1u);
                while (*(volatile unsigned*)&barg[t] < 32u) { }
                __threadfence();
            }
            __syncthreads();
        }
    }
}

// ---------------- final FC ----------------
__global__ __launch_bounds__(256) void fc_partial(
    const float* __restrict__ H2, const float* __restrict__ fcW,
    float* __restrict__ part)
{
    __shared__ float sH[32 * 132];
    __shared__ float sWf[24 * 132];
    const int tid = threadIdx.x;
    const int btile = blockIdx.x;
    const int kc = blockIdx.y;
    const int bl = tid >> 3, osub = tid & 7;
    const size_t KTOT = (size_t)SS * HH;
    float acc[3] = {0.f, 0.f, 0.f};

    for (int k0 = kc * 4096; k0 < kc * 4096 + 4096; k0 += 128) {
#pragma unroll
        for (int i = 0; i < 4; i++) {
            int idx = tid + i * 256;
            int r = idx >> 5, c4 = idx & 31;
            *reinterpret_cast<float4*>(sH + r * 132 + c4 * 4) =
                *reinterpret_cast<const float4*>(H2 + (size_t)(btile * 32 + r) * KTOT + k0 + c4 * 4);
        }
#pragma unroll
        for (int i = 0; i < 3; i++) {
            int idx = tid + i * 256;
            int r = idx >> 5, c4 = idx & 31;
            *reinterpret_cast<float4*>(sWf + r * 132 + c4 * 4) =
                *reinterpret_cast<const float4*>(fcW + (size_t)r * KTOT + k0 + c4 * 4);
        }
        __syncthreads();
#pragma unroll 8
        for (int kk = 0; kk < 128; kk++) {
            float a = sH[bl * 132 + kk];
            acc[0] += a * sWf[(osub * 3 + 0) * 132 + kk];
            acc[1] += a * sWf[(osub * 3 + 1) * 132 + kk];
            acc[2] += a * sWf[(osub * 3 + 2) * 132 + kk];
        }
        __syncthreads();
    }
    int b = btile * 32 + bl;
#pragma unroll
    for (int j = 0; j < 3; j++)
        part[((size_t)kc * 256 + b) * 24 + osub * 3 + j] = acc[j];
}

__global__ void fc_reduce(const float* __restrict__ part, const float* __restrict__ fcb,
                          float* __restrict__ out)
{
    int id = blockIdx.x * 256 + threadIdx.x;
    if (id >= 256 * 24) return;
    int b = id / 24, o = id % 24;
    float s = fcb[o];
#pragma unroll 8
    for (int kc = 0; kc < 128; kc++) s += part[((size_t)kc * 256 + b) * 24 + o];
    out[(size_t)b * 24 + o] = s;
}

// ---------------- launch (7 graph nodes) ----------------
extern "C" void kernel_launch(void* const* d_in, const int* in_sizes, int n_in,
                              void* d_out, int out_size)
{
    const float* x    = (const float*)d_in[0];
    const float* Wih0 = (const float*)d_in[1];
    const float* Whh0 = (const float*)d_in[2];
    const float* bih0 = (const float*)d_in[3];
    const float* bhh0 = (const float*)d_in[4];
    const float* Wih1 = (const float*)d_in[5];
    const float* Whh1 = (const float*)d_in[6];
    const float* bih1 = (const float*)d_in[7];
    const float* bhh1 = (const float*)d_in[8];
    const float* fcW  = (const float*)d_in[9];
    const float* fcb  = (const float*)d_in[10];

    float *H1p, *H2p, *zp, *cp, *pp, *w0p, *w1p;
    unsigned *b0p, *b1p;
    cudaGetSymbolAddress((void**)&H1p, g_H1);
    cudaGetSymbolAddress((void**)&H2p, g_H2);
    cudaGetSymbolAddress((void**)&zp, g_zero);
    cudaGetSymbolAddress((void**)&cp, g_c);
    cudaGetSymbolAddress((void**)&pp, g_part);
    cudaGetSymbolAddress((void**)&w0p, g_Wr0);
    cudaGetSymbolAddress((void**)&w1p, g_Wr1);
    cudaGetSymbolAddress((void**)&b0p, g_bar0);
    cudaGetSymbolAddress((void**)&b1p, g_bar1);

    cudaFuncSetAttribute(lstm_mma<FF>, cudaFuncAttributeMaxDynamicSharedMemorySize, SMEM_BYTES);
    cudaFuncSetAttribute(lstm_mma<HH>, cudaFuncAttributeMaxDynamicSharedMemorySize, SMEM_BYTES);

    bar_reset<<<8, 256>>>();
    {
        size_t tot0 = (size_t)32 * NCH0 * 128 * 32;
        size_t tot1 = (size_t)32 * NCH1 * 128 * 32;
        wcvt<<<(int)((tot0 + 255) / 256), 256>>>(Wih0, Whh0, w0p, FF, NCH0, tot0);
        wcvt<<<(int)((tot1 + 255) / 256), 256>>>(Wih1, Whh1, w1p, HH, NCH1, tot1);
    }

    dim3 grid(32, 4);
    // layer 0: A0(t) = x[:, t, :]; h in H1 [S][B][H]
    lstm_mma<FF><<<grid, 128, SMEM_BYTES>>>(
        x, (size_t)FF, (size_t)SS * FF,
        H1p, (size_t)BB * HH, (size_t)HH,
        zp, w0p, bih0, bhh0,
        cp, H1p, (size_t)BB * HH, (size_t)HH, b0p);
    // layer 1: A0(t) = H1[t]; h in H2 [B][S][H] (FC-ready)
    lstm_mma<HH><<<grid, 128, SMEM_BYTES>>>(
        H1p, (size_t)BB * HH, (size_t)HH,
        H2p, (size_t)HH, (size_t)SS * HH,
        zp, w1p, bih1, bhh1,
        cp, H2p, (size_t)HH, (size_t)SS * HH, b1p);

    fc_partial<<<dim3(8, 128), 256>>>(H2p, fcW, pp);
    fc_reduce<<<24, 256>>>(pp, fcb, (float*)d_out);
}

// round 6
// speedup vs baseline: 1.2306x; 1.0335x over previous
#include <cuda_runtime.h>
#include <cstdint>
#include <cstddef>

#define BB 256
#define SS 512
#define FF 64
#define HH 1024
#define OO 24

#define NCH0 34            // (64+1024)/32
#define NCH1 64            // (1024+1024)/32
#define STAGE_F 6912       // floats per stage: A 64*36 + B 128*36
#define SMEM_BYTES (3 * STAGE_F * 4 + 512)   // 83456

// ---------------- scratch (device globals; no allocs) ----------------
constexpr size_t H_ELEMS = (size_t)SS * BB * HH;
__device__ float g_H1[H_ELEMS];              // layer0 h (tf32-rounded), [S][B][H]
__device__ float g_H2[H_ELEMS];              // layer1 h (tf32-rounded), [B][S][H]
__device__ float g_Xr[(size_t)BB * SS * FF]; // tf32-rounded x
__device__ float g_zero[BB * HH];            // never written
__device__ float g_c[BB * HH];               // cell state (exact fp32)
__device__ float g_part[128 * 256 * 24];     // FC partials
__device__ unsigned g_bar0[4 * SS];
__device__ unsigned g_bar1[4 * SS];
__device__ float g_Wr0[(size_t)32 * NCH0 * 128 * 32];  // permuted tf32 weights L0
__device__ float g_Wr1[(size_t)32 * NCH1 * 128 * 32];  // L1

// ---------------- helpers ----------------
__device__ __forceinline__ unsigned f2tf(float f) {
    unsigned u;
    asm("cvt.rna.tf32.f32 %0, %1;" : "=r"(u) : "f"(f));
    return u;
}
__device__ __forceinline__ void mma8(float* d, const unsigned* a, const unsigned* b) {
    asm volatile(
        "mma.sync.aligned.m16n8k8.row.col.f32.tf32.tf32.f32 "
        "{%0,%1,%2,%3}, {%4,%5,%6,%7}, {%8,%9}, {%0,%1,%2,%3};\n"
        : "+f"(d[0]), "+f"(d[1]), "+f"(d[2]), "+f"(d[3])
        : "r"(a[0]), "r"(a[1]), "r"(a[2]), "r"(a[3]), "r"(b[0]), "r"(b[1]));
}
__device__ __forceinline__ void cpa16(uint32_t dst, const void* src) {
    asm volatile("cp.async.cg.shared.global [%0], [%1], 16;" :: "r"(dst), "l"(src));
}
#define CP_COMMIT() asm volatile("cp.async.commit_group;" ::: "memory")
#define CP_WAIT(n)  asm volatile("cp.async.wait_group %0;" :: "n"(n) : "memory")
__device__ __forceinline__ uint32_t smem_u32(const void* p) {
    uint32_t a;
    asm("{ .reg .u64 t; cvta.to.shared.u64 t, %1; cvt.u32.u64 %0, t; }" : "=r"(a) : "l"(p));
    return a;
}
__device__ __forceinline__ float sigm(float x) { return 1.f / (1.f + __expf(-x)); }
__device__ __forceinline__ float tanh_(float x) {
    float a = fabsf(x);
    float e = __expf(-2.f * a);
    return copysignf((1.f - e) / (1.f + e), x);
}

__global__ void bar_reset() {
    int i = blockIdx.x * blockDim.x + threadIdx.x;
    if (i < 4 * SS) { g_bar0[i] = 0; g_bar1[i] = 0; }
}

// round x to tf32 once (so the GEMM hot loop needs no cvt)
__global__ void xcvt(const float* __restrict__ x, float* __restrict__ dst, size_t n) {
    size_t i = (size_t)blockIdx.x * 256 + threadIdx.x;
    if (i < n) dst[i] = __uint_as_float(f2tf(x[i]));
}

// ---------------- weight convert + permute ----------------
// dst: d = ((ntile*NCH + c)*128 + j)*32 + p ; j = gate*32+hsub ; k(p) = (p&7)*4 + (p>>3)
__global__ void wcvt(const float* __restrict__ Wih, const float* __restrict__ Whh,
                     float* __restrict__ dst, int KIN, int NCH, size_t total)
{
    size_t d = (size_t)blockIdx.x * 256 + threadIdx.x;
    if (d >= total) return;
    int p = (int)(d & 31);
    int j = (int)((d >> 5) & 127);
    int rest = (int)(d >> 12);
    int c = rest % NCH, ntile = rest / NCH;
    int grow = (j >> 5) * HH + ntile * 32 + (j & 31);
    int k = c * 32 + ((p & 7) * 4 + (p >> 3));
    float v = (k < KIN) ? Wih[(size_t)grow * KIN + k]
                        : Whh[(size_t)grow * HH + (k - KIN)];
    dst[d] = __uint_as_float(f2tf(v));
}

// ---------------- persistent mma.sync LSTM layer ----------------
// Grid (32 ntiles, 4 batch groups) = 128 CTAs, 256 threads (8 warps).
// CTA tile M=64 batch x N=128 gate-rows. Warp grid 2(m) x 4(n): warp tile 32x32.
// All activations arriving here are already tf32-rounded -> no cvt in hot loop.
template <int KIN>
__global__ __launch_bounds__(256, 1) void lstm_mma(
    const float* __restrict__ A0base, size_t a0_t, size_t lda0,
    const float* __restrict__ hbase, size_t h_t, size_t ldh,
    const float* __restrict__ zero,
    const float* __restrict__ Wr,
    const float* __restrict__ bih, const float* __restrict__ bhh,
    float* __restrict__ cst,
    float* __restrict__ houtbase, size_t hout_t, size_t hstride,
    unsigned* __restrict__ bar)
{
    constexpr int NCH = (KIN + HH) / 32;
    extern __shared__ float sm[];
    const uint32_t sb = smem_u32(sm);
    const int tid = threadIdx.x;
    const int lane = tid & 31, warp = tid >> 5;
    const int g4 = lane >> 2, tig = lane & 3;
    const int wm = warp & 1;           // batch 32-half
    const int wn = warp >> 1;          // gate (0..3)
    const int ntile = blockIdx.x;
    const int n0h = ntile * 32;
    const int m0 = blockIdx.y * 64;
    unsigned* barg = bar + blockIdx.y * SS;
    float* sBias = sm + 3 * STAGE_F;

    if (tid < 128) {
        int grow = (tid >> 5) * HH + n0h + (tid & 31);
        sBias[tid] = bih[grow] + bhh[grow];
    }
    __syncthreads();

    for (int t = 0; t < SS; ++t) {
        const float* A0 = A0base + (size_t)t * a0_t + (size_t)m0 * lda0;
        const float* Ah = (t == 0) ? (zero + (size_t)m0 * HH)
                                   : (hbase + (size_t)(t - 1) * h_t + (size_t)m0 * ldh);
        const size_t ldah = (t == 0) ? (size_t)HH : ldh;

        auto issue = [&](int c) {
            const int st = c % 3;
            const uint32_t aB = sb + st * STAGE_F * 4;
            const uint32_t bB = aB + 64 * 36 * 4;
            const int k0 = c * 32;
            const float* As; size_t Al; int ka;
            if (k0 < KIN) { As = A0; Al = lda0; ka = k0; }
            else          { As = Ah; Al = ldah; ka = k0 - KIN; }
#pragma unroll
            for (int i = 0; i < 2; i++) {
                int idx = i * 256 + tid;          // 512 float4 segs (64 x 8)
                int r = idx >> 3, c4 = idx & 7;
                cpa16(aB + r * 144 + c4 * 16, As + (size_t)r * Al + ka + c4 * 4);
            }
            const float* Bs = Wr + ((size_t)ntile * NCH + c) * 4096;
#pragma unroll
            for (int i = 0; i < 4; i++) {
                int seg = i * 256 + tid;          // 1024 float4 segs (128 x 8)
                cpa16(bB + (seg >> 3) * 144 + (seg & 7) * 16, Bs + seg * 4);
            }
            CP_COMMIT();
        };

        float acc[2][4][4];
#pragma unroll
        for (int mf = 0; mf < 2; mf++)
#pragma unroll
            for (int nf = 0; nf < 4; nf++)
#pragma unroll
                for (int q = 0; q < 4; q++) acc[mf][nf][q] = 0.f;

        issue(0); issue(1); issue(2);

        for (int c = 0; c < NCH; ++c) {
            if (c < NCH - 2)       { CP_WAIT(2); }
            else if (c == NCH - 2) { CP_WAIT(1); }
            else                   { CP_WAIT(0); }
            __syncthreads();

            const int st = c % 3;
            const float* sA = sm + st * STAGE_F;
            const float* sB = sA + 64 * 36;

            // B (weights): whole chunk per nf, k-permuted -> 2x lds.128
            unsigned bp[4][8];
#pragma unroll
            for (int nf = 0; nf < 4; nf++) {
                const float* base = sB + (wn * 32 + nf * 8 + g4) * 36 + tig * 8;
                uint4 v0 = *reinterpret_cast<const uint4*>(base);
                uint4 v1 = *reinterpret_cast<const uint4*>(base + 4);
                bp[nf][0] = v0.x; bp[nf][1] = v0.y; bp[nf][2] = v0.z; bp[nf][3] = v0.w;
                bp[nf][4] = v1.x; bp[nf][5] = v1.y; bp[nf][6] = v1.z; bp[nf][7] = v1.w;
            }
#pragma unroll
            for (int kk8 = 0; kk8 < 4; kk8++) {
                const int kk = kk8 * 8;
                unsigned a[2][4];
#pragma unroll
                for (int mf = 0; mf < 2; mf++) {
                    int r = wm * 32 + mf * 16 + g4;
                    a[mf][0] = __float_as_uint(sA[r * 36 + kk + tig]);
                    a[mf][1] = __float_as_uint(sA[(r + 8) * 36 + kk + tig]);
                    a[mf][2] = __float_as_uint(sA[r * 36 + kk + tig + 4]);
                    a[mf][3] = __float_as_uint(sA[(r + 8) * 36 + kk + tig + 4]);
                }
#pragma unroll
                for (int mf = 0; mf < 2; mf++)
#pragma unroll
                    for (int nf = 0; nf < 4; nf++) {
                        unsigned b2[2] = { bp[nf][kk8 * 2], bp[nf][kk8 * 2 + 1] };
                        mma8(acc[mf][nf], a[mf], b2);
                    }
            }
            __syncthreads();
            if (c + 3 < NCH) issue(c + 3);
        }

        // ---- epilogue: bounce accs through smem ----
        float* sC = sm;   // [4 gates][64 b][32 h] = 32KB (stages drained)
#pragma unroll
        for (int mf = 0; mf < 2; mf++) {
            int r = wm * 32 + mf * 16 + g4;
#pragma unroll
            for (int nf = 0; nf < 4; nf++) {
                int col = nf * 8 + 2 * tig;
                *reinterpret_cast<float2*>(&sC[wn * 2048 + r * 32 + col]) =
                    make_float2(acc[mf][nf][0], acc[mf][nf][1]);
                *reinterpret_cast<float2*>(&sC[wn * 2048 + (r + 8) * 32 + col]) =
                    make_float2(acc[mf][nf][2], acc[mf][nf][3]);
            }
        }
        __syncthreads();

        float* hout = houtbase + (size_t)t * hout_t;
#pragma unroll
        for (int it = 0; it < 2; it++) {
            int idx4 = it * 256 + tid;
            int bl = idx4 >> 3, h4 = (idx4 & 7) * 4;
            float4 gi = *reinterpret_cast<float4*>(&sC[0 * 2048 + bl * 32 + h4]);
            float4 gf = *reinterpret_cast<float4*>(&sC[1 * 2048 + bl * 32 + h4]);
            float4 gg = *reinterpret_cast<float4*>(&sC[2 * 2048 + bl * 32 + h4]);
            float4 go = *reinterpret_cast<float4*>(&sC[3 * 2048 + bl * 32 + h4]);
            float4 b0 = *reinterpret_cast<float4*>(&sBias[0 * 32 + h4]);
            float4 b1 = *reinterpret_cast<float4*>(&sBias[32 + h4]);
            float4 b2 = *reinterpret_cast<float4*>(&sBias[64 + h4]);
            float4 b3 = *reinterpret_cast<float4*>(&sBias[96 + h4]);
            size_t b = (size_t)(m0 + bl);
            float4 cold = (t == 0) ? make_float4(0.f, 0.f, 0.f, 0.f)
                                   : *reinterpret_cast<float4*>(&cst[b * HH + n0h + h4]);
            float4 cn, hn;
            {
                float ci = sigm(gi.x + b0.x), cf = sigm(gf.x + b1.x);
                float cg = tanh_(gg.x + b2.x), co = sigm(go.x + b3.x);
                cn.x = cf * cold.x + ci * cg;
                hn.x = __uint_as_float(f2tf(co * tanh_(cn.x)));
            }
            {
                float ci = sigm(gi.y + b0.y), cf = sigm(gf.y + b1.y);
                float cg = tanh_(gg.y + b2.y), co = sigm(go.y + b3.y);
                cn.y = cf * cold.y + ci * cg;
                hn.y = __uint_as_float(f2tf(co * tanh_(cn.y)));
            }
            {
                float ci = sigm(gi.z + b0.z), cf = sigm(gf.z + b1.z);
                float cg = tanh_(gg.z + b2.z), co = sigm(go.z + b3.z);
                cn.z = cf * cold.z + ci * cg;
                hn.z = __uint_as_float(f2tf(co * tanh_(cn.z)));
            }
            {
                float ci = sigm(gi.w + b0.w), cf = sigm(gf.w + b1.w);
                float cg = tanh_(gg.w + b2.w), co = sigm(go.w + b3.w);
                cn.w = cf * cold.w + ci * cg;
                hn.w = __uint_as_float(f2tf(co * tanh_(cn.w)));
            }
            *reinterpret_cast<float4*>(&cst[b * HH + n0h + h4]) = cn;
            *reinterpret_cast<float4*>(&hout[b * hstride + n0h + h4]) = hn;
        }
        __syncthreads();

        if (t + 1 < SS) {
            __threadfence();
            if (tid == 0) {
                atomicAdd(&barg[t], 1u);
                while (*(volatile unsigned*)&barg[t] < 32u) { }
                __threadfence();
            }
            __syncthreads();
        }
    }
}

// ---------------- final FC ----------------
__global__ __launch_bounds__(256) void fc_partial(
    const float* __restrict__ H2, const float* __restrict__ fcW,
    float* __restrict__ part)
{
    __shared__ float sH[32 * 132];
    __shared__ float sWf[24 * 132];
    const int tid = threadIdx.x;
    const int btile = blockIdx.x;
    const int kc = blockIdx.y;
    const int bl = tid >> 3, osub = tid & 7;
    const size_t KTOT = (size_t)SS * HH;
    float acc[3] = {0.f, 0.f, 0.f};

    for (int k0 = kc * 4096; k0 < kc * 4096 + 4096; k0 += 128) {
#pragma unroll
        for (int i = 0; i < 4; i++) {
            int idx = tid + i * 256;
            int r = idx >> 5, c4 = idx & 31;
            *reinterpret_cast<float4*>(sH + r * 132 + c4 * 4) =
                *reinterpret_cast<const float4*>(H2 + (size_t)(btile * 32 + r) * KTOT + k0 + c4 * 4);
        }
#pragma unroll
        for (int i = 0; i < 3; i++) {
            int idx = tid + i * 256;
            int r = idx >> 5, c4 = idx & 31;
            *reinterpret_cast<float4*>(sWf + r * 132 + c4 * 4) =
                *reinterpret_cast<const float4*>(fcW + (size_t)r * KTOT + k0 + c4 * 4);
        }
        __syncthreads();
#pragma unroll 8
        for (int kk = 0; kk < 128; kk++) {
            float a = sH[bl * 132 + kk];
            acc[0] += a * sWf[(osub * 3 + 0) * 132 + kk];
            acc[1] += a * sWf[(osub * 3 + 1) * 132 + kk];
            acc[2] += a * sWf[(osub * 3 + 2) * 132 + kk];
        }
        __syncthreads();
    }
    int b = btile * 32 + bl;
#pragma unroll
    for (int j = 0; j < 3; j++)
        part[((size_t)kc * 256 + b) * 24 + osub * 3 + j] = acc[j];
}

__global__ void fc_reduce(const float* __restrict__ part, const float* __restrict__ fcb,
                          float* __restrict__ out)
{
    int id = blockIdx.x * 256 + threadIdx.x;
    if (id >= 256 * 24) return;
    int b = id / 24, o = id % 24;
    float s = fcb[o];
#pragma unroll 8
    for (int kc = 0; kc < 128; kc++) s += part[((size_t)kc * 256 + b) * 24 + o];
    out[(size_t)b * 24 + o] = s;
}

// ---------------- launch (8 graph nodes) ----------------
extern "C" void kernel_launch(void* const* d_in, const int* in_sizes, int n_in,
                              void* d_out, int out_size)
{
    const float* x    = (const float*)d_in[0];
    const float* Wih0 = (const float*)d_in[1];
    const float* Whh0 = (const float*)d_in[2];
    const float* bih0 = (const float*)d_in[3];
    const float* bhh0 = (const float*)d_in[4];
    const float* Wih1 = (const float*)d_in[5];
    const float* Whh1 = (const float*)d_in[6];
    const float* bih1 = (const float*)d_in[7];
    const float* bhh1 = (const float*)d_in[8];
    const float* fcW  = (const float*)d_in[9];
    const float* fcb  = (const float*)d_in[10];

    float *H1p, *H2p, *zp, *cp, *pp, *w0p, *w1p, *xrp;
    unsigned *b0p, *b1p;
    cudaGetSymbolAddress((void**)&H1p, g_H1);
    cudaGetSymbolAddress((void**)&H2p, g_H2);
    cudaGetSymbolAddress((void**)&zp, g_zero);
    cudaGetSymbolAddress((void**)&cp, g_c);
    cudaGetSymbolAddress((void**)&pp, g_part);
    cudaGetSymbolAddress((void**)&w0p, g_Wr0);
    cudaGetSymbolAddress((void**)&w1p, g_Wr1);
    cudaGetSymbolAddress((void**)&xrp, g_Xr);
    cudaGetSymbolAddress((void**)&b0p, g_bar0);
    cudaGetSymbolAddress((void**)&b1p, g_bar1);

    cudaFuncSetAttribute(lstm_mma<FF>, cudaFuncAttributeMaxDynamicSharedMemorySize, SMEM_BYTES);
    cudaFuncSetAttribute(lstm_mma<HH>, cudaFuncAttributeMaxDynamicSharedMemorySize, SMEM_BYTES);

    bar_reset<<<8, 256>>>();
    {
        size_t tot0 = (size_t)32 * NCH0 * 128 * 32;
        size_t tot1 = (size_t)32 * NCH1 * 128 * 32;
        wcvt<<<(int)((tot0 + 255) / 256), 256>>>(Wih0, Whh0, w0p, FF, NCH0, tot0);
        wcvt<<<(int)((tot1 + 255) / 256), 256>>>(Wih1, Whh1, w1p, HH, NCH1, tot1);
        size_t nx = (size_t)BB * SS * FF;
        xcvt<<<(int)((nx + 255) / 256), 256>>>(x, xrp, nx);
    }

    dim3 grid(32, 4);
    // layer 0: A0(t) = Xr[:, t, :]; h in H1 [S][B][H]
    lstm_mma<FF><<<grid, 256, SMEM_BYTES>>>(
        xrp, (size_t)FF, (size_t)SS * FF,
        H1p, (size_t)BB * HH, (size_t)HH,
        zp, w0p, bih0, bhh0,
        cp, H1p, (size_t)BB * HH, (size_t)HH, b0p);
    // layer 1: A0(t) = H1[t]; h in H2 [B][S][H] (FC-ready)
    lstm_mma<HH><<<grid, 256, SMEM_BYTES>>>(
        H1p, (size_t)BB * HH, (size_t)HH,
        H2p, (size_t)HH, (size_t)SS * HH,
        zp, w1p, bih1, bhh1,
        cp, H2p, (size_t)HH, (size_t)SS * HH, b1p);

    fc_partial<<<dim3(8, 128), 256>>>(H2p, fcW, pp);
    fc_reduce<<<24, 256>>>(pp, fcb, (float*)d_out);
}

// round 9
// speedup vs baseline: 2.3290x; 1.8927x over previous
#include <cuda_runtime.h>
#include <cuda_fp16.h>
#include <cstdint>
#include <cstddef>

#define BB 256
#define SS 512
#define FF 64
#define HH 1024
#define OO 24

#define NCH0T 34           // 2 + 32 chunks of K=32
#define NCH1T 64           // 32 + 32
#define STAGE_B 12288      // A 4KB fp16 + B 8KB fp16
#define NST 5
#define SMEM_BYTES (NST * STAGE_B + 512)   // 61952

// ---------------- scratch (device globals; no allocs) ----------------
__device__ __half g_P1h[(size_t)SS * 4 * 32 * 2048];   // h1 perm fp16 [t][bg][chunk][64][32]
__device__ __half g_P2h[(size_t)SS * 4 * 32 * 2048];   // h2 perm fp16
__device__ __half g_Xp[(size_t)SS * 4 * 2 * 2048];     // x perm fp16
__device__ float  g_H2[(size_t)SS * BB * HH];          // h2 flat fp32 [B][S][H] for FC
__device__ float  g_zero[2048];                        // never written (also zero halves)
__device__ float  g_c[BB * HH];                        // cell state fp32
__device__ float  g_part[128 * 256 * 24];              // FC partials
__device__ unsigned g_bar0[4 * SS];
__device__ unsigned g_bar1[4 * SS];
__device__ __half g_Wh0[(size_t)32 * NCH0T * 128 * 32];  // permuted fp16 weights L0
__device__ __half g_Wh1[(size_t)32 * NCH1T * 128 * 32];  // L1

// ---------------- helpers ----------------
// perm: position p <- k : p = ((k>>1)&3)*8 + ((k>>4)&1)*4 + ((k>>3)&1)*2 + (k&1)
// inverse: k(p) = 2*((p>>3)&3) + (p&1) + 8*((p>>1)&1) + 16*((p>>2)&1)
__device__ __forceinline__ int kofp(int p) {
    return 2 * ((p >> 3) & 3) + (p & 1) + 8 * ((p >> 1) & 1) + 16 * ((p >> 2) & 1);
}
__device__ __forceinline__ void mma16(float* d,
    unsigned a0, unsigned a1, unsigned a2, unsigned a3, unsigned b0, unsigned b1) {
    asm volatile(
        "mma.sync.aligned.m16n8k16.row.col.f32.f16.f16.f32 "
        "{%0,%1,%2,%3}, {%4,%5,%6,%7}, {%8,%9}, {%0,%1,%2,%3};\n"
        : "+f"(d[0]), "+f"(d[1]), "+f"(d[2]), "+f"(d[3])
        : "r"(a0), "r"(a1), "r"(a2), "r"(a3), "r"(b0), "r"(b1));
}
__device__ __forceinline__ void cpa16(uint32_t dst, const void* src) {
    asm volatile("cp.async.cg.shared.global [%0], [%1], 16;" :: "r"(dst), "l"(src));
}
#define CP_COMMIT() asm volatile("cp.async.commit_group;" ::: "memory")
#define CP_WAIT(n)  asm volatile("cp.async.wait_group %0;" :: "n"(n) : "memory")
__device__ __forceinline__ uint32_t smem_u32(const void* p) {
    uint32_t a;
    asm("{ .reg .u64 t; cvta.to.shared.u64 t, %1; cvt.u32.u64 %0, t; }" : "=r"(a) : "l"(p));
    return a;
}
__device__ __forceinline__ float sigm(float x) { return 1.f / (1.f + __expf(-x)); }
__device__ __forceinline__ float tanh_(float x) {
    float a = fabsf(x);
    float e = __expf(-2.f * a);
    return copysignf((1.f - e) / (1.f + e), x);
}

__global__ void bar_reset() {
    int i = blockIdx.x * blockDim.x + threadIdx.x;
    if (i < 4 * SS) { g_bar0[i] = 0; g_bar1[i] = 0; }
}

// weights -> fp16, permuted: dst[((ntile*NCH + c)*128 + j)*32 + p], j = gate*32 + hsub
__global__ void wcvt(const float* __restrict__ Wih, const float* __restrict__ Whh,
                     __half* __restrict__ dst, int KIN, int NCH, size_t total)
{
    size_t d = (size_t)blockIdx.x * 256 + threadIdx.x;
    if (d >= total) return;
    int p = (int)(d & 31);
    int j = (int)((d >> 5) & 127);
    int rest = (int)(d >> 12);
    int c = rest % NCH, ntile = rest / NCH;
    int grow = (j >> 5) * HH + ntile * 32 + (j & 31);
    int k = c * 32 + kofp(p);
    float v = (k < KIN) ? Wih[(size_t)grow * KIN + k]
                        : Whh[(size_t)grow * HH + (k - KIN)];
    dst[d] = __float2half(v);
}

// x -> fp16, permuted chunk layout [t][bg][c(2)][row 64][perm 32]
__global__ void xprep(const float* __restrict__ x, __half* __restrict__ dst)
{
    size_t d = (size_t)blockIdx.x * 256 + threadIdx.x;
    if (d >= (size_t)SS * 4 * 2 * 2048) return;
    int p = (int)(d & 31);
    int row = (int)((d >> 5) & 63);
    int c = (int)((d >> 11) & 1);
    int bg = (int)((d >> 12) & 3);
    int t = (int)(d >> 14);
    int k = c * 32 + kofp(p);
    int b = bg * 64 + row;
    dst[d] = __float2half(x[(size_t)b * SS * FF + (size_t)t * FF + k]);
}

// ---------------- persistent fp16 mma LSTM layer ----------------
// Grid (32 ntiles, 4 batch groups) = 128 CTAs, 256 thr (8 warps), warp tile 32x32.
// CTA: M=64 batch x N=128 gate-rows, K = (KCHIN+32) chunks of 32.
template <int KCHIN>
__global__ __launch_bounds__(256, 1) void lstm_fp16(
    const __half* __restrict__ A0p,     // input chunks:    ((t*4+bg)*KCHIN + c)*2048
    const __half* __restrict__ A1p,     // recurrent:       (((t-1)*4+bg)*32 + c-KCHIN)*2048
    const __half* __restrict__ zeroh,
    const __half* __restrict__ Wp,      // ((ntile*NCH + c))*4096
    const float* __restrict__ bih, const float* __restrict__ bhh,
    float* __restrict__ cst,
    __half* __restrict__ hperm,         // ((t*4+bg)*32 + ntile)*2048
    float* __restrict__ hflat,          // [B][S][H] fp32 (layer1 only)
    unsigned* __restrict__ bar)
{
    constexpr int NCH = KCHIN + 32;
    constexpr bool WF = (KCHIN == 32);  // layer1 writes flat fp32 too
    extern __shared__ char smc[];
    const uint32_t sb = smem_u32(smc);
    const int tid = threadIdx.x, lane = tid & 31, warp = tid >> 5;
    const int g4 = lane >> 2, tig = lane & 3;
    const int wm = warp & 1, wn = warp >> 1;
    const int ntile = blockIdx.x, bg = blockIdx.y;
    const int n0h = ntile * 32, m0 = bg * 64;
    unsigned* barg = bar + bg * SS;
    float* sBias = (float*)(smc + NST * STAGE_B);

    if (tid < 128) {
        int grow = (tid >> 5) * HH + n0h + (tid & 31);
        sBias[tid] = bih[grow] + bhh[grow];
    }
    __syncthreads();

    for (int t = 0; t < SS; ++t) {
        const __half* a0b = A0p + (size_t)(t * 4 + bg) * KCHIN * 2048;
        const __half* a1b;
        size_t a1s;
        if (t == 0) { a1b = zeroh; a1s = 0; }
        else        { a1b = A1p + (size_t)((t - 1) * 4 + bg) * 32 * 2048; a1s = 2048; }

        auto issue = [&](int c) {
            int st = c % NST;
            uint32_t sa = sb + st * STAGE_B, sw = sa + 4096;
            const __half* src = (c < KCHIN) ? (a0b + (size_t)c * 2048)
                                            : (a1b + (size_t)(c - KCHIN) * a1s);
            cpa16(sa + tid * 16, src + tid * 8);
            const __half* ws = Wp + ((size_t)ntile * NCH + c) * 4096;
            cpa16(sw + tid * 16, ws + tid * 8);
            cpa16(sw + (tid + 256) * 16, ws + (tid + 256) * 8);
            CP_COMMIT();
        };

        float acc[2][4][4];
#pragma unroll
        for (int mf = 0; mf < 2; mf++)
#pragma unroll
            for (int nf = 0; nf < 4; nf++)
#pragma unroll
                for (int q = 0; q < 4; q++) acc[mf][nf][q] = 0.f;

        issue(0); issue(1); issue(2); issue(3);
        int iss = 4;

        for (int c = 0; c < NCH; ++c) {
            int pend = iss - c;
            if (pend >= 4)      { CP_WAIT(3); }
            else if (pend == 3) { CP_WAIT(2); }
            else if (pend == 2) { CP_WAIT(1); }
            else                { CP_WAIT(0); }
            __syncthreads();

            const char* sa = smc + (c % NST) * STAGE_B;
            const char* sw = sa + 4096;

            uint4 bq[4];
#pragma unroll
            for (int nf = 0; nf < 4; nf++)
                bq[nf] = *reinterpret_cast<const uint4*>(sw + (wn * 32 + nf * 8 + g4) * 64 + tig * 16);
            uint4 alo[2], ahi[2];
#pragma unroll
            for (int mf = 0; mf < 2; mf++) {
                alo[mf] = *reinterpret_cast<const uint4*>(sa + (wm * 32 + mf * 16 + g4) * 64 + tig * 16);
                ahi[mf] = *reinterpret_cast<const uint4*>(sa + (wm * 32 + mf * 16 + g4 + 8) * 64 + tig * 16);
            }
#pragma unroll
            for (int mf = 0; mf < 2; mf++)
#pragma unroll
                for (int nf = 0; nf < 4; nf++) {
                    mma16(acc[mf][nf], alo[mf].x, ahi[mf].x, alo[mf].y, ahi[mf].y,
                          bq[nf].x, bq[nf].y);
                    mma16(acc[mf][nf], alo[mf].z, ahi[mf].z, alo[mf].w, ahi[mf].w,
                          bq[nf].z, bq[nf].w);
                }
            if (iss < NCH) { issue(iss); ++iss; }
        }
        __syncthreads();

        // ---- epilogue: bounce accs through smem (aliases stages, all drained) ----
        float* sC = (float*)smc;   // [4 gates][64 b][32 h]
#pragma unroll
        for (int mf = 0; mf < 2; mf++) {
            int r = wm * 32 + mf * 16 + g4;
#pragma unroll
            for (int nf = 0; nf < 4; nf++) {
                int col = nf * 8 + 2 * tig;
                *reinterpret_cast<float2*>(&sC[wn * 2048 + r * 32 + col]) =
                    make_float2(acc[mf][nf][0], acc[mf][nf][1]);
                *reinterpret_cast<float2*>(&sC[wn * 2048 + (r + 8) * 32 + col]) =
                    make_float2(acc[mf][nf][2], acc[mf][nf][3]);
            }
        }
        __syncthreads();

        __half* permb = hperm + ((size_t)(t * 4 + bg) * 32 + ntile) * 2048;
#pragma unroll
        for (int it = 0; it < 2; it++) {
            int idx4 = it * 256 + tid;
            int bl = idx4 >> 3, q = idx4 & 7, h4 = q * 4;
            float4 gi = *reinterpret_cast<float4*>(&sC[0 * 2048 + bl * 32 + h4]);
            float4 gf = *reinterpret_cast<float4*>(&sC[1 * 2048 + bl * 32 + h4]);
            float4 gg = *reinterpret_cast<float4*>(&sC[2 * 2048 + bl * 32 + h4]);
            float4 go = *reinterpret_cast<float4*>(&sC[3 * 2048 + bl * 32 + h4]);
            float4 b0 = *reinterpret_cast<float4*>(&sBias[0 + h4]);
            float4 b1 = *reinterpret_cast<float4*>(&sBias[32 + h4]);
            float4 b2 = *reinterpret_cast<float4*>(&sBias[64 + h4]);
            float4 b3 = *reinterpret_cast<float4*>(&sBias[96 + h4]);
            size_t b = (size_t)(m0 + bl);
            float4 cold = (t == 0) ? make_float4(0.f, 0.f, 0.f, 0.f)
                                   : *reinterpret_cast<float4*>(&cst[b * HH + n0h + h4]);
            float4 cn, hn;
            {
                float ci = sigm(gi.x + b0.x), cf = sigm(gf.x + b1.x);
                float cg = tanh_(gg.x + b2.x), co = sigm(go.x + b3.x);
                cn.x = cf * cold.x + ci * cg; hn.x = co * tanh_(cn.x);
            }
            {
                float ci = sigm(gi.y + b0.y), cf = sigm(gf.y + b1.y);
                float cg = tanh_(gg.y + b2.y), co = sigm(go.y + b3.y);
                cn.y = cf * cold.y + ci * cg; hn.y = co * tanh_(cn.y);
            }
            {
                float ci = sigm(gi.z + b0.z), cf = sigm(gf.z + b1.z);
                float cg = tanh_(gg.z + b2.z), co = sigm(go.z + b3.z);
                cn.z = cf * cold.z + ci * cg; hn.z = co * tanh_(cn.z);
            }
            {
                float ci = sigm(gi.w + b0.w), cf = sigm(gf.w + b1.w);
                float cg = tanh_(gg.w + b2.w), co = sigm(go.w + b3.w);
                cn.w = cf * cold.w + ci * cg; hn.w = co * tanh_(cn.w);
            }
            *reinterpret_cast<float4*>(&cst[b * HH + n0h + h4]) = cn;
            if (WF)
                *reinterpret_cast<float4*>(&hflat[(b * SS + (size_t)t) * HH + n0h + h4]) = hn;
            // permuted fp16 store for next-step GEMM operand
            int base2 = ((q >> 2) & 1) * 4 + ((q >> 1) & 1) * 2;
            int pos1 = ((2 * q) & 3) * 8 + base2;
            int pos2 = ((2 * q + 1) & 3) * 8 + base2;
            *reinterpret_cast<__half2*>(permb + bl * 32 + pos1) = __floats2half2_rn(hn.x, hn.y);
            *reinterpret_cast<__half2*>(permb + bl * 32 + pos2) = __floats2half2_rn(hn.z, hn.w);
        }
        __syncthreads();

        if (t + 1 < SS) {
            __threadfence();
            if (tid == 0) {
                atomicAdd(&barg[t], 1u);
                while (*(volatile unsigned*)&barg[t] < 32u) { }
                __threadfence();
            }
            __syncthreads();
        }
    }
}

// ---------------- final FC (fp32 H2 flat) ----------------
__global__ __launch_bounds__(256) void fc_partial(
    const float* __restrict__ H2, const float* __restrict__ fcW,
    float* __restrict__ part)
{
    __shared__ float sH[32 * 132];
    __shared__ float sWf[24 * 132];
    const int tid = threadIdx.x;
    const int btile = blockIdx.x;
    const int kc = blockIdx.y;
    const int bl = tid >> 3, osub = tid & 7;
    const size_t KTOT = (size_t)SS * HH;
    float acc[3] = {0.f, 0.f, 0.f};

    for (int k0 = kc * 4096; k0 < kc * 4096 + 4096; k0 += 128) {
#pragma unroll
        for (int i = 0; i < 4; i++) {
            int idx = tid + i * 256;
            int r = idx >> 5, c4 = idx & 31;
            *reinterpret_cast<float4*>(sH + r * 132 + c4 * 4) =
                *reinterpret_cast<const float4*>(H2 + (size_t)(btile * 32 + r) * KTOT + k0 + c4 * 4);
        }
#pragma unroll
        for (int i = 0; i < 3; i++) {
            int idx = tid + i * 256;
            int r = idx >> 5, c4 = idx & 31;
            *reinterpret_cast<float4*>(sWf + r * 132 + c4 * 4) =
                *reinterpret_cast<const float4*>(fcW + (size_t)r * KTOT + k0 + c4 * 4);
        }
        __syncthreads();
#pragma unroll 8
        for (int kk = 0; kk < 128; kk++) {
            float a = sH[bl * 132 + kk];
            acc[0] += a * sWf[(osub * 3 + 0) * 132 + kk];
            acc[1] += a * sWf[(osub * 3 + 1) * 132 + kk];
            acc[2] += a * sWf[(osub * 3 + 2) * 132 + kk];
        }
        __syncthreads();
    }
    int b = btile * 32 + bl;
#pragma unroll
    for (int j = 0; j < 3; j++)
        part[((size_t)kc * 256 + b) * 24 + osub * 3 + j] = acc[j];
}

__global__ void fc_reduce(const float* __restrict__ part, const float* __restrict__ fcb,
                          float* __restrict__ out)
{
    int id = blockIdx.x * 256 + threadIdx.x;
    if (id >= 256 * 24) return;
    int b = id / 24, o = id % 24;
    float s = fcb[o];
#pragma unroll 8
    for (int kc = 0; kc < 128; kc++) s += part[((size_t)kc * 256 + b) * 24 + o];
    out[(size_t)b * 24 + o] = s;
}

// ---------------- launch (8 graph nodes) ----------------
extern "C" void kernel_launch(void* const* d_in, const int* in_sizes, int n_in,
                              void* d_out, int out_size)
{
    const float* x    = (const float*)d_in[0];
    const float* Wih0 = (const float*)d_in[1];
    const float* Whh0 = (const float*)d_in[2];
    const float* bih0 = (const float*)d_in[3];
    const float* bhh0 = (const float*)d_in[4];
    const float* Wih1 = (const float*)d_in[5];
    const float* Whh1 = (const float*)d_in[6];
    const float* bih1 = (const float*)d_in[7];
    const float* bhh1 = (const float*)d_in[8];
    const float* fcW  = (const float*)d_in[9];
    const float* fcb  = (const float*)d_in[10];

    float *H2p, *zp, *cp, *pp;
    __half *p1h, *p2h, *xp, *wh0, *wh1;
    unsigned *b0p, *b1p;
    cudaGetSymbolAddress((void**)&H2p, g_H2);
    cudaGetSymbolAddress((void**)&zp, g_zero);
    cudaGetSymbolAddress((void**)&cp, g_c);
    cudaGetSymbolAddress((void**)&pp, g_part);
    cudaGetSymbolAddress((void**)&p1h, g_P1h);
    cudaGetSymbolAddress((void**)&p2h, g_P2h);
    cudaGetSymbolAddress((void**)&xp, g_Xp);
    cudaGetSymbolAddress((void**)&wh0, g_Wh0);
    cudaGetSymbolAddress((void**)&wh1, g_Wh1);
    cudaGetSymbolAddress((void**)&b0p, g_bar0);
    cudaGetSymbolAddress((void**)&b1p, g_bar1);

    cudaFuncSetAttribute(lstm_fp16<2>,  cudaFuncAttributeMaxDynamicSharedMemorySize, SMEM_BYTES);
    cudaFuncSetAttribute(lstm_fp16<32>, cudaFuncAttributeMaxDynamicSharedMemorySize, SMEM_BYTES);

    bar_reset<<<8, 256>>>();
    {
        size_t tot0 = (size_t)32 * NCH0T * 128 * 32;
        size_t tot1 = (size_t)32 * NCH1T * 128 * 32;
        wcvt<<<(int)((tot0 + 255) / 256), 256>>>(Wih0, Whh0, wh0, FF, NCH0T, tot0);
        wcvt<<<(int)((tot1 + 255) / 256), 256>>>(Wih1, Whh1, wh1, HH, NCH1T, tot1);
        size_t nx = (size_t)SS * 4 * 2 * 2048;
        xprep<<<(int)((nx + 255) / 256), 256>>>(x, xp);
    }

    dim3 grid(32, 4);
    // layer 0: input = x perm (2 chunks), recurrent = h1 perm; output h1 perm
    lstm_fp16<2><<<grid, 256, SMEM_BYTES>>>(
        xp, p1h, (const __half*)zp, wh0, bih0, bhh0,
        cp, p1h, nullptr, b0p);
    // layer 1: input = h1 perm (32 chunks), recurrent = h2 perm; output h2 perm + flat fp32
    lstm_fp16<32><<<grid, 256, SMEM_BYTES>>>(
        p1h, p2h, (const __half*)zp, wh1, bih1, bhh1,
        cp, p2h, H2p, b1p);

    fc_partial<<<dim3(8, 128), 256>>>(H2p, fcW, pp);
    fc_reduce<<<24, 256>>>(pp, fcb, (float*)d_out);
}